// round 4
// baseline (speedup 1.0000x reference)
#include <cuda_runtime.h>
#include <cuda_bf16.h>
#include <math.h>

// ----------------------------------------------------------------------------
// QSP: u = Rz(phi0) * prod_{k=1..127} [ Wx(theta) * Rz(phi_k) ]; output
// (Re u00, Im u00) per theta.
//
// Laurent form: u00(theta) = sum_{j=0..127} alpha_j * w^(2j-127),  w = e^{i th}.
// coef_kernel computes alpha_j (depends only on phis).
// eval_kernel: u00 = w^-127 * Horner(alpha, z), z = w^2 — EIGHT rows per
// thread as 4 independent fma.rn.f32x2 (FFMA2) chains, so one LDS.128 of
// duplicated coefficients feeds 16 FFMA2 (smem crossbar at ~50% of cap
// instead of 200% oversubscribed).
// ----------------------------------------------------------------------------

__device__ float2 g_coef[128];

// ---- packed f32x2 helpers ---------------------------------------------------
#define FMA2(d, a, b, c) \
    asm("fma.rn.f32x2 %0, %1, %2, %3;" : "=l"(d) : "l"(a), "l"(b), "l"(c))
#define PACK2(d, lo, hi) \
    asm("mov.b64 %0, {%1, %2};" : "=l"(d) : "f"(lo), "f"(hi))
#define UNPACK2(lo, hi, s) \
    asm("mov.b64 {%0, %1}, %2;" : "=f"(lo), "=f"(hi) : "l"(s))

// ---- Kernel 1: compute Laurent coefficients (1 block, 256 threads) ----------
// State indexed by m = exponent + 127 (0..254), stored at slot m+1 in padded
// [258] arrays so m-1 / m+1 neighbor reads never go out of bounds.
__global__ void coef_kernel(const float* __restrict__ phis)
{
    __shared__ float2 e[128];
    __shared__ float2 Abuf[2][258];
    __shared__ float2 Bbuf[2][258];

    const int t = threadIdx.x;  // 0..255

    if (t < 128) {
        float s, c;
        sincosf(phis[t], &s, &c);
        e[t] = make_float2(c, s);   // e_k = exp(i phi_k)
    }

    const float2 z2 = make_float2(0.f, 0.f);
    Abuf[0][t + 1] = z2; Abuf[1][t + 1] = z2;
    Bbuf[0][t + 1] = z2; Bbuf[1][t + 1] = z2;
    if (t == 0) {
        Abuf[0][0] = z2; Abuf[0][257] = z2;
        Abuf[1][0] = z2; Abuf[1][257] = z2;
        Bbuf[0][0] = z2; Bbuf[0][257] = z2;
        Bbuf[1][0] = z2; Bbuf[1][257] = z2;
    }
    __syncthreads();

    if (t == 127) Abuf[0][128] = e[0];  // A = e0 at exponent 0
    __syncthreads();

    int cur = 0;
    for (int k = 1; k <= 127; ++k) {
        const float2 ek = e[k];
        const int m = t + 1;

        const float2 Al = Abuf[cur][m - 1];
        const float2 Bl = Bbuf[cur][m - 1];
        const float2 Ar = Abuf[cur][m + 1];
        const float2 Br = Bbuf[cur][m + 1];

        const float sr = Al.x + Bl.x, si = Al.y + Bl.y;   // (A+B) @ m-1
        const float dr = Ar.x - Br.x, di = Ar.y - Br.y;   // (A-B) @ m+1

        const float ur = 0.5f * (sr + dr), ui = 0.5f * (si + di);
        const float vr = 0.5f * (sr - dr), vi = 0.5f * (si - di);

        const int nxt = cur ^ 1;
        Abuf[nxt][m] = make_float2(ur * ek.x - ui * ek.y,
                                   ur * ek.y + ui * ek.x);   // e_k * u
        Bbuf[nxt][m] = make_float2(vr * ek.x + vi * ek.y,
                                   vi * ek.x - vr * ek.y);   // conj(e_k) * v
        cur = nxt;
        __syncthreads();
    }

    if (t < 128) g_coef[t] = Abuf[cur][2 * t + 1];  // exponent 2j-127 -> slot 2j+1
}

// ---- Kernel 2: Horner evaluation, 8 rows/thread as 4 f32x2 chains -----------
__global__ void __launch_bounds__(256)
eval_kernel(const float4* __restrict__ th4, float* __restrict__ out, int n)
{
    // sc[j] = (Cx, Cx, Cy, Cy): one LDS.128 broadcast yields both packed
    // constants in aligned 64-bit register pairs for all 4 chains.
    __shared__ float4 sc[128];
    if (threadIdx.x < 128) {
        const float2 c = g_coef[threadIdx.x];
        sc[threadIdx.x] = make_float4(c.x, c.x, c.y, c.y);
    }
    __syncthreads();

    const int ng = n >> 3;  // groups of 8 rows
    const int i = blockIdx.x * blockDim.x + threadIdx.x;
    if (i >= ng) return;

    const float4 ta = th4[2 * i];       // rows 8i .. 8i+3
    const float4 tb = th4[2 * i + 1];   // rows 8i+4 .. 8i+7
    float th[8] = {ta.x, ta.y, ta.z, ta.w, tb.x, tb.y, tb.z, tb.w};

    // packed per-pair constants for z = w^2 rotation
    unsigned long long c2p[4], s2p[4], ns2p[4];
#pragma unroll
    for (int p = 0; p < 4; ++p) {
        float sa, ca, sb, cb;
        sincosf(2.0f * th[2 * p],     &sa, &ca);
        sincosf(2.0f * th[2 * p + 1], &sb, &cb);
        PACK2(c2p[p],  ca,  cb);
        PACK2(s2p[p],  sa,  sb);
        PACK2(ns2p[p], -sa, -sb);
    }

    const ulonglong2* scv = reinterpret_cast<const ulonglong2*>(sc);

    ulonglong2 C = scv[127];
    unsigned long long ar[4], ai[4];
#pragma unroll
    for (int p = 0; p < 4; ++p) { ar[p] = C.x; ai[p] = C.y; }

#pragma unroll 8
    for (int j = 126; j >= 0; --j) {
        C = scv[j];                          // one LDS.128 per 16 FFMA2
#pragma unroll
        for (int p = 0; p < 4; ++p) {
            unsigned long long t0, t1;
            FMA2(t0, ai[p], ns2p[p], C.x);   // -ai*s2 + Cx
            FMA2(t1, ar[p], s2p[p],  C.y);   //  ar*s2 + Cy
            FMA2(ar[p], ar[p], c2p[p], t0);  //  ar*c2 + t0
            FMA2(ai[p], ai[p], c2p[p], t1);  //  ai*c2 + t1
        }
    }

    // final rotation by w^-127 = (cos(127t), -sin(127t)); computed after the
    // loop so the 16 phase values never inflate loop-live registers.
    float re[8], im[8];
#pragma unroll
    for (int p = 0; p < 4; ++p) {
        float arA, arB, aiA, aiB;
        UNPACK2(arA, arB, ar[p]);
        UNPACK2(aiA, aiB, ai[p]);
        float sp, cp;
        sincosf(127.0f * th[2 * p], &sp, &cp);
        re[2 * p]     = fmaf(aiA, sp,  arA * cp);
        im[2 * p]     = fmaf(aiA, cp, -arA * sp);
        sincosf(127.0f * th[2 * p + 1], &sp, &cp);
        re[2 * p + 1] = fmaf(aiB, sp,  arB * cp);
        im[2 * p + 1] = fmaf(aiB, cp, -arB * sp);
    }

    float4* outr = reinterpret_cast<float4*>(out);
    float4* outi = reinterpret_cast<float4*>(out + n);
    outr[2 * i]     = make_float4(re[0], re[1], re[2], re[3]);
    outr[2 * i + 1] = make_float4(re[4], re[5], re[6], re[7]);
    outi[2 * i]     = make_float4(im[0], im[1], im[2], im[3]);
    outi[2 * i + 1] = make_float4(im[4], im[5], im[6], im[7]);
}

// ---- launch -----------------------------------------------------------------
extern "C" void kernel_launch(void* const* d_in, const int* in_sizes, int n_in,
                              void* d_out, int out_size)
{
    const float* th   = (const float*)d_in[0];
    const float* phis = (const float*)d_in[1];
    float* out = (float*)d_out;
    const int n = in_sizes[0];  // B rows (multiple of 8)

    coef_kernel<<<1, 256>>>(phis);

    const int ng = n >> 3;
    eval_kernel<<<(ng + 255) / 256, 256>>>(
        reinterpret_cast<const float4*>(th), out, n);
}

// round 6
// speedup vs baseline: 2.1213x; 2.1213x over previous
#include <cuda_runtime.h>
#include <cuda_bf16.h>
#include <math.h>

// ----------------------------------------------------------------------------
// QSP: u = Rz(phi0) * prod_{k=1..127} [ Wx(theta) * Rz(phi_k) ]; output
// (Re u00, Im u00) per theta.
//
// u00(theta) = sum_j alpha_j e^{i(2j-127)theta} is band-limited (B=127).
// Pipeline:
//   1) coef_kernel : Laurent coefficients alpha_j from phis (1 block).
//   2) grid_kernel : exact Horner eval of u00 on a uniform theta-grid,
//                    h = pi/6136 (6140 nodes incl. 1-left/2-right guard).
//   3) interp_kernel: per-row 4-point Lagrange (cubic) interpolation from
//                    the grid held in 48KB shared. Truncation error
//                    (127h)^4/24 ~ 7e-7 << 1e-3 tolerance.
// ----------------------------------------------------------------------------

#define GRID_N   6136
#define GRID_PTS (GRID_N + 4)   // nodes -1 .. GRID_N+2 ; node i at slot i+1

__device__ float2 g_coef[128];
__device__ float2 g_grid[GRID_PTS];

// ---- Kernel 1: Laurent coefficients (1 block, 256 threads) ------------------
// State indexed by m = exponent + 127 (0..254), stored at slot m+1 in padded
// [258] arrays so m-1 / m+1 neighbor reads never go out of bounds.
__global__ void coef_kernel(const float* __restrict__ phis)
{
    __shared__ float2 e[128];
    __shared__ float2 Abuf[2][258];
    __shared__ float2 Bbuf[2][258];

    const int t = threadIdx.x;  // 0..255

    if (t < 128) {
        float s, c;
        sincosf(phis[t], &s, &c);
        e[t] = make_float2(c, s);   // e_k = exp(i phi_k)
    }

    const float2 z2 = make_float2(0.f, 0.f);
    Abuf[0][t + 1] = z2; Abuf[1][t + 1] = z2;
    Bbuf[0][t + 1] = z2; Bbuf[1][t + 1] = z2;
    if (t == 0) {
        Abuf[0][0] = z2; Abuf[0][257] = z2;
        Abuf[1][0] = z2; Abuf[1][257] = z2;
        Bbuf[0][0] = z2; Bbuf[0][257] = z2;
        Bbuf[1][0] = z2; Bbuf[1][257] = z2;
    }
    __syncthreads();

    if (t == 127) Abuf[0][128] = e[0];  // A = e0 at exponent 0
    __syncthreads();

    int cur = 0;
    for (int k = 1; k <= 127; ++k) {
        const float2 ek = e[k];
        const int m = t + 1;

        const float2 Al = Abuf[cur][m - 1];
        const float2 Bl = Bbuf[cur][m - 1];
        const float2 Ar = Abuf[cur][m + 1];
        const float2 Br = Bbuf[cur][m + 1];

        const float sr = Al.x + Bl.x, si = Al.y + Bl.y;   // (A+B) @ m-1
        const float dr = Ar.x - Br.x, di = Ar.y - Br.y;   // (A-B) @ m+1

        const float ur = 0.5f * (sr + dr), ui = 0.5f * (si + di);
        const float vr = 0.5f * (sr - dr), vi = 0.5f * (si - di);

        const int nxt = cur ^ 1;
        Abuf[nxt][m] = make_float2(ur * ek.x - ui * ek.y,
                                   ur * ek.y + ui * ek.x);   // e_k * u
        Bbuf[nxt][m] = make_float2(vr * ek.x + vi * ek.y,
                                   vi * ek.x - vr * ek.y);   // conj(e_k) * v
        cur = nxt;
        __syncthreads();
    }

    if (t < 128) g_coef[t] = Abuf[cur][2 * t + 1];  // exponent 2j-127 -> slot 2j+1
}

// ---- Kernel 2: exact Horner eval on the uniform grid ------------------------
__global__ void __launch_bounds__(256)
grid_kernel()
{
    __shared__ float2 sc[128];
    if (threadIdx.x < 128) sc[threadIdx.x] = g_coef[threadIdx.x];
    __syncthreads();

    const int i = blockIdx.x * blockDim.x + threadIdx.x;
    if (i >= GRID_PTS) return;

    const double hd = 3.14159265358979323846 / (double)GRID_N;
    const float t = (float)((double)(i - 1) * hd);   // node index i-1

    float s2, c2;  sincosf(2.0f * t, &s2, &c2);      // z = w^2
    float sp, cp;  sincosf(127.0f * t, &sp, &cp);    // w^127 phase

    float ar = sc[127].x;
    float ai = sc[127].y;
#pragma unroll 16
    for (int j = 126; j >= 0; --j) {
        const float2 C = sc[j];
        const float nr = fmaf(-ai, s2, fmaf(ar, c2, C.x));
        const float ni = fmaf( ai, c2, fmaf(ar, s2, C.y));
        ar = nr;
        ai = ni;
    }
    // multiply by w^-127 = (cos(127t), -sin(127t))
    g_grid[i] = make_float2(fmaf(ai, sp,  ar * cp),
                            fmaf(ai, cp, -ar * sp));
}

// ---- Kernel 3: cubic Lagrange interpolation, 2 rows/thread/iter -------------
__global__ void __launch_bounds__(256, 4)
interp_kernel(const float2* __restrict__ th2, float* __restrict__ out, int n)
{
    __shared__ float2 G[GRID_PTS];   // 49120 B (static, <=48KB)
    for (int i = threadIdx.x; i < GRID_PTS; i += 256)
        G[i] = g_grid[i];
    __syncthreads();

    // invh = GRID_N / pi, split for an accurate fractional position
    constexpr double INVH_D  = (double)GRID_N / 3.14159265358979323846;
    const float invh_hi = (float)INVH_D;
    const float invh_lo = (float)(INVH_D - (double)invh_hi);

    const int np = n >> 1;
    const int stride = gridDim.x * blockDim.x;
    float2* outr = reinterpret_cast<float2*>(out);
    float2* outi = reinterpret_cast<float2*>(out + n);

    for (int g = blockIdx.x * blockDim.x + threadIdx.x; g < np; g += stride) {
        const float2 tt = th2[g];
        float2 re, im;

#pragma unroll
        for (int r = 0; r < 2; ++r) {
            const float t = (r == 0) ? tt.x : tt.y;

            // u = t/h with ~1e-7 accuracy in the fraction
            const float p  = t * invh_hi;
            const float kf = floorf(p);
            const float e  = fmaf(t, invh_hi, -p) + t * invh_lo;
            const float f  = (p - kf) + e;
            const int   k  = (int)kf;          // nodes k-1..k+2 -> slots k..k+3

            // 4-point Lagrange weights at offset f in {-1,0,1,2}
            const float fm1 = f - 1.0f, fm2 = f - 2.0f, fp1 = f + 1.0f;
            const float t1  = f * fm1;          // f(f-1)
            const float t2  = fp1 * fm2;        // (f+1)(f-2)
            const float wm1 = (t1 * fm2) * (-1.0f / 6.0f);
            const float w2  = (t1 * fp1) * ( 1.0f / 6.0f);
            const float w0  = (t2 * fm1) * 0.5f;
            const float w1  = (t2 * f  ) * (-0.5f);

            const float2 g0 = G[k];
            const float2 g1 = G[k + 1];
            const float2 g2 = G[k + 2];
            const float2 g3 = G[k + 3];

            const float vr = fmaf(wm1, g0.x, fmaf(w0, g1.x, fmaf(w1, g2.x, w2 * g3.x)));
            const float vi = fmaf(wm1, g0.y, fmaf(w0, g1.y, fmaf(w1, g2.y, w2 * g3.y)));
            if (r == 0) { re.x = vr; im.x = vi; }
            else        { re.y = vr; im.y = vi; }
        }

        outr[g] = re;   // rows 2g, 2g+1
        outi[g] = im;
    }
}

// ---- launch -----------------------------------------------------------------
extern "C" void kernel_launch(void* const* d_in, const int* in_sizes, int n_in,
                              void* d_out, int out_size)
{
    const float* th   = (const float*)d_in[0];
    const float* phis = (const float*)d_in[1];
    float* out = (float*)d_out;
    const int n = in_sizes[0];  // B rows (even)

    coef_kernel<<<1, 256>>>(phis);
    grid_kernel<<<(GRID_PTS + 255) / 256, 256>>>();

    const int blocks = 592;     // 4 per SM (48KB smem each)
    interp_kernel<<<blocks, 256>>>(
        reinterpret_cast<const float2*>(th), out, n);
}

// round 7
// speedup vs baseline: 2.5085x; 1.1825x over previous
#include <cuda_runtime.h>
#include <cuda_bf16.h>
#include <math.h>

// ----------------------------------------------------------------------------
// QSP: u = Rz(phi0) * prod_{k=1..127} [ Wx(theta) * Rz(phi_k) ]; output
// (Re u00, Im u00) per theta.
//
// u00(theta) = sum_j alpha_j e^{i(2j-127)theta} is band-limited (B=127).
// Pipeline:
//   1) coef_kernel : Laurent coefficients alpha_j from phis — SINGLE WARP,
//                    compressed indexing (A_j^k = coeff of exponent 2j-k),
//                    recurrence A'_j = (e_k/2)[(A+B)_{j-1} + (A-B)_j],
//                               B'_j = (conj(e_k)/2)[(A+B)_{j-1} - (A-B)_j],
//                    4 slots/lane, boundary via __shfl_up_sync. No barriers.
//   2) grid_kernel : exact Horner eval of u00 on a uniform theta-grid,
//                    h = pi/6136 (6140 nodes incl. 1-left/2-right guard).
//   3) interp_kernel: per-row 4-point Lagrange (cubic) interpolation from
//                    the grid held in 48KB shared. Truncation error
//                    (127h)^4/24 ~ 7e-7 << 1e-3 tolerance.
// ----------------------------------------------------------------------------

#define GRID_N   6136
#define GRID_PTS (GRID_N + 4)   // nodes -1 .. GRID_N+2 ; node i at slot i+1

__device__ float2 g_coef[128];
__device__ float2 g_grid[GRID_PTS];

// ---- Kernel 1: Laurent coefficients (1 block, 32 threads, warp-sync) --------
__global__ void coef_kernel(const float* __restrict__ phis)
{
    __shared__ float2 e[128];

    const int lane = threadIdx.x;  // 0..31

    // each lane computes 4 of the e_k = exp(i phi_k)
#pragma unroll
    for (int q = 0; q < 4; ++q) {
        const int k = lane * 4 + q;
        float s, c;
        sincosf(phis[k], &s, &c);
        e[k] = make_float2(c, s);
    }
    __syncwarp();

    // state: lane owns slots j = 4*lane + q, q = 0..3
    float Ar[4] = {0.f, 0.f, 0.f, 0.f}, Ai[4] = {0.f, 0.f, 0.f, 0.f};
    float Br[4] = {0.f, 0.f, 0.f, 0.f}, Bi[4] = {0.f, 0.f, 0.f, 0.f};

    if (lane == 0) {            // k=0 state: A_0 = e_0 (exponent 0)
        const float2 e0 = e[0];
        Ar[0] = e0.x; Ai[0] = e0.y;
    }

    for (int k = 1; k <= 127; ++k) {
        const float2 ek = e[k];
        const float ehr = 0.5f * ek.x;
        const float ehi = 0.5f * ek.y;

        float sr[4], si[4], dr[4], di[4];
#pragma unroll
        for (int q = 0; q < 4; ++q) {
            sr[q] = Ar[q] + Br[q];  si[q] = Ai[q] + Bi[q];
            dr[q] = Ar[q] - Br[q];  di[q] = Ai[q] - Bi[q];
        }

        // boundary: (A+B) at slot 4*lane-1 comes from lane-1's slot 3
        float smr = __shfl_up_sync(0xffffffffu, sr[3], 1);
        float smi = __shfl_up_sync(0xffffffffu, si[3], 1);
        if (lane == 0) { smr = 0.f; smi = 0.f; }

#pragma unroll
        for (int q = 0; q < 4; ++q) {
            const float spr = (q == 0) ? smr : sr[q - 1];
            const float spi = (q == 0) ? smi : si[q - 1];

            const float ur = spr + dr[q], ui = spi + di[q];
            const float vr = spr - dr[q], vi = spi - di[q];

            // A' = (e/2) * u ; B' = conj(e/2) * v
            Ar[q] = fmaf(ehr, ur, -ehi * ui);
            Ai[q] = fmaf(ehr, ui,  ehi * ur);
            Br[q] = fmaf(ehr, vr,  ehi * vi);
            Bi[q] = fmaf(ehr, vi, -ehi * vr);
        }
    }

#pragma unroll
    for (int q = 0; q < 4; ++q)
        g_coef[lane * 4 + q] = make_float2(Ar[q], Ai[q]);
}

// ---- Kernel 2: exact Horner eval on the uniform grid ------------------------
__global__ void __launch_bounds__(256)
grid_kernel()
{
    __shared__ float2 sc[128];
    if (threadIdx.x < 128) sc[threadIdx.x] = g_coef[threadIdx.x];
    __syncthreads();

    const int i = blockIdx.x * blockDim.x + threadIdx.x;
    if (i >= GRID_PTS) return;

    const double hd = 3.14159265358979323846 / (double)GRID_N;
    const float t = (float)((double)(i - 1) * hd);   // node index i-1

    float s2, c2;  sincosf(2.0f * t, &s2, &c2);      // z = w^2
    float sp, cp;  sincosf(127.0f * t, &sp, &cp);    // w^127 phase

    float ar = sc[127].x;
    float ai = sc[127].y;
#pragma unroll 16
    for (int j = 126; j >= 0; --j) {
        const float2 C = sc[j];
        const float nr = fmaf(-ai, s2, fmaf(ar, c2, C.x));
        const float ni = fmaf( ai, c2, fmaf(ar, s2, C.y));
        ar = nr;
        ai = ni;
    }
    // multiply by w^-127 = (cos(127t), -sin(127t))
    g_grid[i] = make_float2(fmaf(ai, sp,  ar * cp),
                            fmaf(ai, cp, -ar * sp));
}

// ---- Kernel 3: cubic Lagrange interpolation, 2 rows/thread/iter -------------
__global__ void __launch_bounds__(256, 4)
interp_kernel(const float2* __restrict__ th2, float* __restrict__ out, int n)
{
    __shared__ float2 G[GRID_PTS];   // 49120 B (static, <=48KB)
    for (int i = threadIdx.x; i < GRID_PTS; i += 256)
        G[i] = g_grid[i];
    __syncthreads();

    // invh = GRID_N / pi, split for an accurate fractional position
    constexpr double INVH_D  = (double)GRID_N / 3.14159265358979323846;
    const float invh_hi = (float)INVH_D;
    const float invh_lo = (float)(INVH_D - (double)invh_hi);

    const int np = n >> 1;
    const int stride = gridDim.x * blockDim.x;
    float2* outr = reinterpret_cast<float2*>(out);
    float2* outi = reinterpret_cast<float2*>(out + n);

    for (int g = blockIdx.x * blockDim.x + threadIdx.x; g < np; g += stride) {
        const float2 tt = th2[g];
        float2 re, im;

#pragma unroll
        for (int r = 0; r < 2; ++r) {
            const float t = (r == 0) ? tt.x : tt.y;

            // u = t/h with ~1e-7 accuracy in the fraction
            const float p  = t * invh_hi;
            const float kf = floorf(p);
            const float e  = fmaf(t, invh_hi, -p) + t * invh_lo;
            const float f  = (p - kf) + e;
            const int   k  = (int)kf;          // nodes k-1..k+2 -> slots k..k+3

            // 4-point Lagrange weights at offset f in {-1,0,1,2}
            const float fm1 = f - 1.0f, fm2 = f - 2.0f, fp1 = f + 1.0f;
            const float t1  = f * fm1;          // f(f-1)
            const float t2  = fp1 * fm2;        // (f+1)(f-2)
            const float wm1 = (t1 * fm2) * (-1.0f / 6.0f);
            const float w2  = (t1 * fp1) * ( 1.0f / 6.0f);
            const float w0  = (t2 * fm1) * 0.5f;
            const float w1  = (t2 * f  ) * (-0.5f);

            const float2 g0 = G[k];
            const float2 g1 = G[k + 1];
            const float2 g2 = G[k + 2];
            const float2 g3 = G[k + 3];

            const float vr = fmaf(wm1, g0.x, fmaf(w0, g1.x, fmaf(w1, g2.x, w2 * g3.x)));
            const float vi = fmaf(wm1, g0.y, fmaf(w0, g1.y, fmaf(w1, g2.y, w2 * g3.y)));
            if (r == 0) { re.x = vr; im.x = vi; }
            else        { re.y = vr; im.y = vi; }
        }

        outr[g] = re;   // rows 2g, 2g+1
        outi[g] = im;
    }
}

// ---- launch -----------------------------------------------------------------
extern "C" void kernel_launch(void* const* d_in, const int* in_sizes, int n_in,
                              void* d_out, int out_size)
{
    const float* th   = (const float*)d_in[0];
    const float* phis = (const float*)d_in[1];
    float* out = (float*)d_out;
    const int n = in_sizes[0];  // B rows (even)

    coef_kernel<<<1, 32>>>(phis);
    grid_kernel<<<(GRID_PTS + 255) / 256, 256>>>();

    const int blocks = 592;     // 4 per SM (48KB smem each)
    interp_kernel<<<blocks, 256>>>(
        reinterpret_cast<const float2*>(th), out, n);
}

// round 8
// speedup vs baseline: 2.9020x; 1.1569x over previous
#include <cuda_runtime.h>
#include <cuda_bf16.h>
#include <math.h>

// ----------------------------------------------------------------------------
// QSP: u = Rz(phi0) * prod_{k=1..127} [ Wx(theta) * Rz(phi_k) ]; output
// (Re u00, Im u00) per theta.
//
// Pipeline:
//  1) coef_kernel : split the 128-factor product into 4 chunks of ~32 factors.
//     Each chunk C_m = prod(Wx*Rz) keeps the QSP symmetry
//     C = [[A,B],[-conj(B), conj(A)]] (on |w|=1), so its first-row Laurent
//     coefficients (A_m, B_m) fully describe it. 4 independent warps run the
//     compressed shift recurrence (~32 steps each) — no barriers, depth/4.
//  2) grid_kernel : at each theta-node evaluate each chunk's (A_m, B_m) by a
//     33-step complex Horner in z=w^2, apply phase w^{-L_m}, and compose the
//     4 rows:  (a,b) <- (a*A - b*conj(B), a*B + b*conj(A)).  u00 = a.
//  3) interp_kernel: cubic Lagrange interpolation from the grid in 24.5KB
//     shared (8 blocks/SM). Truncation ~0.0234*(127h)^4 ~ 6.7e-6 << 1e-3.
// ----------------------------------------------------------------------------

#define GRID_N   3064
#define GRID_PTS (GRID_N + 4)   // nodes -1 .. GRID_N+2 ; node i at slot i+1

#define NCHUNK 4
#define CSLOTS 33               // max coeff slots per chunk (32 factors -> 33)

__device__ float4 g_cc[NCHUNK * CSLOTS];   // (Ar, Ai, Br, Bi) per slot
__device__ float2 g_grid[GRID_PTS];

// ---- Kernel 1: chunk Laurent coefficients (1 block, 128 threads = 4 warps) --
// Warp w owns chunk w. Chunk 0 = Rz(phi0) * prod_{k=1..31}(Wx Rz(phi_k)),
// chunks 1..3 = prod over phis[32w .. 32w+31]. State = first row (A,B) in
// compressed indexing (slot s holds exponent 2s - j after j factors):
//   A'_s = (e/2) [ (A+B)_{s-1} + (A-B)_s ],
//   B'_s = (conj(e)/2) [ (A+B)_{s-1} - (A-B)_s ].
__global__ void coef_kernel(const float* __restrict__ phis)
{
    __shared__ float2 e[NCHUNK][32];

    const int tid  = threadIdx.x;
    const int w    = tid >> 5;
    const int lane = tid & 31;

    {
        float s, c;
        sincosf(phis[w * 32 + lane], &s, &c);
        e[w][lane] = make_float2(c, s);
    }
    __syncwarp();

    // 2 slots per lane: slot = 2*lane + q
    float Ar[2] = {0.f, 0.f}, Ai[2] = {0.f, 0.f};
    float Br[2] = {0.f, 0.f}, Bi[2] = {0.f, 0.f};

    int kstart;
    if (w == 0) {           // leading Rz(phi0): A = e_phi0 at exponent 0
        if (lane == 0) { Ar[0] = e[0][0].x; Ai[0] = e[0][0].y; }
        kstart = 1;
    } else {                // identity init: A = 1 at exponent 0
        if (lane == 0) { Ar[0] = 1.f; }
        kstart = 0;
    }

    for (int k = kstart; k < 32; ++k) {
        const float2 ek = e[w][k];
        const float ehr = 0.5f * ek.x;
        const float ehi = 0.5f * ek.y;

        float sr[2], si[2], dr[2], di[2];
#pragma unroll
        for (int q = 0; q < 2; ++q) {
            sr[q] = Ar[q] + Br[q];  si[q] = Ai[q] + Bi[q];
            dr[q] = Ar[q] - Br[q];  di[q] = Ai[q] - Bi[q];
        }

        // (A+B) at slot 2*lane-1 comes from lane-1's slot 1
        float smr = __shfl_up_sync(0xffffffffu, sr[1], 1);
        float smi = __shfl_up_sync(0xffffffffu, si[1], 1);
        if (lane == 0) { smr = 0.f; smi = 0.f; }

#pragma unroll
        for (int q = 0; q < 2; ++q) {
            const float spr = (q == 0) ? smr : sr[0];
            const float spi = (q == 0) ? smi : si[0];

            const float ur = spr + dr[q], ui = spi + di[q];
            const float vr = spr - dr[q], vi = spi - di[q];

            Ar[q] = fmaf(ehr, ur, -ehi * ui);
            Ai[q] = fmaf(ehr, ui,  ehi * ur);
            Br[q] = fmaf(ehr, vr,  ehi * vi);
            Bi[q] = fmaf(ehr, vi, -ehi * vr);
        }
    }

#pragma unroll
    for (int q = 0; q < 2; ++q) {
        const int slot = 2 * lane + q;
        if (slot < CSLOTS)
            g_cc[w * CSLOTS + slot] = make_float4(Ar[q], Ai[q], Br[q], Bi[q]);
    }
}

// ---- Kernel 2: exact eval on the uniform grid via chunk composition ---------
__global__ void __launch_bounds__(256)
grid_kernel()
{
    __shared__ float4 sc[NCHUNK * CSLOTS];
    if (threadIdx.x < NCHUNK * CSLOTS) sc[threadIdx.x] = g_cc[threadIdx.x];
    __syncthreads();

    const int i = blockIdx.x * blockDim.x + threadIdx.x;
    if (i >= GRID_PTS) return;

    const double hd = 3.14159265358979323846 / (double)GRID_N;
    const float t = (float)((double)(i - 1) * hd);   // node index i-1

    float s2, c2;   sincosf(2.0f  * t, &s2,  &c2);   // z = w^2
    float s31, c31; sincosf(31.0f * t, &s31, &c31);  // w^31 phase (chunk 0)
    float s32, c32; sincosf(32.0f * t, &s32, &c32);  // w^32 phase (chunks 1-3)

    float ur = 0.f, ui = 0.f, vr = 0.f, vi = 0.f;    // running row (a,b)

#pragma unroll
    for (int m = 0; m < NCHUNK; ++m) {
        const float4* C = sc + m * CSLOTS;

        // Horner in z for both chunk polynomials P_A, P_B
        float4 c = C[CSLOTS - 1];
        float ar = c.x, ai = c.y, br = c.z, bi = c.w;
#pragma unroll
        for (int j = CSLOTS - 2; j >= 0; --j) {
            c = C[j];
            const float nar = fmaf(-ai, s2, fmaf(ar, c2, c.x));
            const float nai = fmaf( ai, c2, fmaf(ar, s2, c.y));
            const float nbr = fmaf(-bi, s2, fmaf(br, c2, c.z));
            const float nbi = fmaf( bi, c2, fmaf(br, s2, c.w));
            ar = nar; ai = nai; br = nbr; bi = nbi;
        }

        // apply w^{-L_m}: (cp, -sp)
        const float cp = (m == 0) ? c31 : c32;
        const float sp = (m == 0) ? s31 : s32;
        const float AR = fmaf(ai, sp,  ar * cp);
        const float AI = fmaf(ai, cp, -ar * sp);
        const float BR = fmaf(bi, sp,  br * cp);
        const float BI = fmaf(bi, cp, -br * sp);

        if (m == 0) {
            ur = AR; ui = AI; vr = BR; vi = BI;
        } else {
            // (a,b) <- (a*A - b*conj(B), a*B + b*conj(A))
            const float nar = fmaf(ur, AR, fmaf(-ui, AI, fmaf(-vr, BR, -vi * BI)));
            const float nai = fmaf(ur, AI, fmaf( ui, AR, fmaf( vr, BI, -vi * BR)));
            const float nbr = fmaf(ur, BR, fmaf(-ui, BI, fmaf( vr, AR,  vi * AI)));
            const float nbi = fmaf(ur, BI, fmaf( ui, BR, fmaf( vi, AR, -vr * AI)));
            ur = nar; ui = nai; vr = nbr; vi = nbi;
        }
    }

    g_grid[i] = make_float2(ur, ui);   // u00 at this node
}

// ---- Kernel 3: cubic Lagrange interpolation, 2 rows/thread/iter -------------
__global__ void __launch_bounds__(256, 8)
interp_kernel(const float2* __restrict__ th2, float* __restrict__ out, int n)
{
    __shared__ float2 G[GRID_PTS];   // 24544 B -> up to 8 blocks/SM
    for (int i = threadIdx.x; i < GRID_PTS; i += 256)
        G[i] = g_grid[i];
    __syncthreads();

    // invh = GRID_N / pi, split for an accurate fractional position
    constexpr double INVH_D  = (double)GRID_N / 3.14159265358979323846;
    const float invh_hi = (float)INVH_D;
    const float invh_lo = (float)(INVH_D - (double)invh_hi);

    const int np = n >> 1;
    const int stride = gridDim.x * blockDim.x;
    float2* outr = reinterpret_cast<float2*>(out);
    float2* outi = reinterpret_cast<float2*>(out + n);

    for (int g = blockIdx.x * blockDim.x + threadIdx.x; g < np; g += stride) {
        const float2 tt = th2[g];
        float2 re, im;

#pragma unroll
        for (int r = 0; r < 2; ++r) {
            const float t = (r == 0) ? tt.x : tt.y;

            // u = t/h with ~1e-7 accuracy in the fraction
            const float p  = t * invh_hi;
            const float kf = floorf(p);
            const float e  = fmaf(t, invh_hi, -p) + t * invh_lo;
            const float f  = (p - kf) + e;
            const int   k  = (int)kf;          // nodes k-1..k+2 -> slots k..k+3

            // 4-point Lagrange weights at offset f in {-1,0,1,2}
            const float fm1 = f - 1.0f, fm2 = f - 2.0f, fp1 = f + 1.0f;
            const float t1  = f * fm1;          // f(f-1)
            const float t2  = fp1 * fm2;        // (f+1)(f-2)
            const float wm1 = (t1 * fm2) * (-1.0f / 6.0f);
            const float w2  = (t1 * fp1) * ( 1.0f / 6.0f);
            const float w0  = (t2 * fm1) * 0.5f;
            const float w1  = (t2 * f  ) * (-0.5f);

            const float2 g0 = G[k];
            const float2 g1 = G[k + 1];
            const float2 g2 = G[k + 2];
            const float2 g3 = G[k + 3];

            const float vr = fmaf(wm1, g0.x, fmaf(w0, g1.x, fmaf(w1, g2.x, w2 * g3.x)));
            const float vi = fmaf(wm1, g0.y, fmaf(w0, g1.y, fmaf(w1, g2.y, w2 * g3.y)));
            if (r == 0) { re.x = vr; im.x = vi; }
            else        { re.y = vr; im.y = vi; }
        }

        outr[g] = re;   // rows 2g, 2g+1
        outi[g] = im;
    }
}

// ---- launch -----------------------------------------------------------------
extern "C" void kernel_launch(void* const* d_in, const int* in_sizes, int n_in,
                              void* d_out, int out_size)
{
    const float* th   = (const float*)d_in[0];
    const float* phis = (const float*)d_in[1];
    float* out = (float*)d_out;
    const int n = in_sizes[0];  // B rows (even)

    coef_kernel<<<1, 128>>>(phis);
    grid_kernel<<<(GRID_PTS + 255) / 256, 256>>>();

    const int blocks = 148 * 8;   // 8 per SM (24.5KB smem each)
    interp_kernel<<<blocks, 256>>>(
        reinterpret_cast<const float2*>(th), out, n);
}

// round 9
// speedup vs baseline: 3.3002x; 1.1372x over previous
#include <cuda_runtime.h>
#include <cuda_bf16.h>
#include <math.h>

// ----------------------------------------------------------------------------
// QSP: u = Rz(phi0) * prod_{k=1..127} [ Wx(theta) * Rz(phi_k) ]; output
// (Re u00, Im u00) per theta.
//
// Pipeline (2 launches):
//  1) fused_grid_kernel: per block, 8 warps each build one chunk of the
//     product (chunk0 = Rz(phi0)*prod of 15 Wx*Rz, chunks 1..7 = 16 factors)
//     via the compressed shift recurrence (1 slot/lane, shfl only), then the
//     block evaluates u00 exactly on its slice of a uniform theta-grid:
//     per chunk a 17-slot complex Horner in z=w^2 + phase w^{-L}, composed
//     through the QSP symmetry C = [[A,B],[-conj B, conj A]].
//  2) interp_kernel: cubic Lagrange interpolation from the grid in 16.4KB
//     shared. Truncation ~0.0234*(127h)^4 ~ 3.4e-5 << 1e-3 tolerance.
// ----------------------------------------------------------------------------

#define GRID_N   2048
#define GRID_PTS (GRID_N + 4)   // nodes -1 .. GRID_N+2 ; node i at slot i+1

#define NCHUNK 8
#define CSLOTS 17               // 16 factors -> degree 16 -> 17 slots

__device__ float2 g_grid[GRID_PTS];

// ---- Kernel 1: fused coefficients + grid evaluation -------------------------
__global__ void __launch_bounds__(256)
fused_grid_kernel(const float* __restrict__ phis)
{
    __shared__ float4 sc[NCHUNK * CSLOTS];   // (Ar,Ai,Br,Bi) per slot

    const int tid  = threadIdx.x;
    const int w    = tid >> 5;    // chunk id, 0..7
    const int lane = tid & 31;

    // --- chunk coefficients, warp-synchronous (every block redundantly) ---
    // lane l holds e_{w*16+l} = exp(i phi); broadcast per step via shfl.
    float er = 1.f, ei = 0.f;
    if (lane < 16) {
        float s, c;
        sincosf(phis[w * 16 + lane], &s, &c);
        er = c; ei = s;
    }

    // state: slot = lane (slots 0..16 live; higher lanes stay zero)
    float Ar = 0.f, Ai = 0.f, Br = 0.f, Bi = 0.f;
    int kstart;
    if (w == 0) {                 // leading Rz(phi0): A = e_{phi0} at slot 0
        if (lane == 0) { Ar = er; Ai = ei; }
        kstart = 1;               // factors use phis[1..15]
    } else {
        if (lane == 0) { Ar = 1.f; }
        kstart = 0;               // factors use phis[16w .. 16w+15]
    }

    for (int k = kstart; k < 16; ++k) {
        const float ekr = __shfl_sync(0xffffffffu, er, k);
        const float eki = __shfl_sync(0xffffffffu, ei, k);
        const float ehr = 0.5f * ekr;
        const float ehi = 0.5f * eki;

        const float sr = Ar + Br, si = Ai + Bi;
        const float dr = Ar - Br, di = Ai - Bi;

        float spr = __shfl_up_sync(0xffffffffu, sr, 1);
        float spi = __shfl_up_sync(0xffffffffu, si, 1);
        if (lane == 0) { spr = 0.f; spi = 0.f; }

        const float ur = spr + dr, ui = spi + di;
        const float vr = spr - dr, vi = spi - di;

        Ar = fmaf(ehr, ur, -ehi * ui);   // A' = (e/2) u
        Ai = fmaf(ehr, ui,  ehi * ur);
        Br = fmaf(ehr, vr,  ehi * vi);   // B' = conj(e/2) v
        Bi = fmaf(ehr, vi, -ehi * vr);
    }

    if (lane < CSLOTS)
        sc[w * CSLOTS + lane] = make_float4(Ar, Ai, Br, Bi);
    __syncthreads();

    // --- exact eval at this thread's grid node ---
    const int i = blockIdx.x * blockDim.x + tid;
    if (i >= GRID_PTS) return;

    const double hd = 3.14159265358979323846 / (double)GRID_N;
    const float t = (float)((double)(i - 1) * hd);   // node index i-1

    float s2, c2;   sincosf(2.0f  * t, &s2,  &c2);   // z = w^2
    float s15, c15; sincosf(15.0f * t, &s15, &c15);  // w^15 (chunk 0, L=15)
    float s16, c16; sincosf(16.0f * t, &s16, &c16);  // w^16 (chunks 1-7, L=16)

    float ur = 0.f, ui = 0.f, vr = 0.f, vi = 0.f;    // running row (a,b)

#pragma unroll
    for (int m = 0; m < NCHUNK; ++m) {
        const float4* C = sc + m * CSLOTS;

        float4 c = C[CSLOTS - 1];
        float ar = c.x, ai = c.y, br = c.z, bi = c.w;
#pragma unroll
        for (int j = CSLOTS - 2; j >= 0; --j) {
            c = C[j];
            const float nar = fmaf(-ai, s2, fmaf(ar, c2, c.x));
            const float nai = fmaf( ai, c2, fmaf(ar, s2, c.y));
            const float nbr = fmaf(-bi, s2, fmaf(br, c2, c.z));
            const float nbi = fmaf( bi, c2, fmaf(br, s2, c.w));
            ar = nar; ai = nai; br = nbr; bi = nbi;
        }

        // apply w^{-L_m}: (cp, -sp)
        const float cp = (m == 0) ? c15 : c16;
        const float sp = (m == 0) ? s15 : s16;
        const float AR = fmaf(ai, sp,  ar * cp);
        const float AI = fmaf(ai, cp, -ar * sp);
        const float BR = fmaf(bi, sp,  br * cp);
        const float BI = fmaf(bi, cp, -br * sp);

        if (m == 0) {
            ur = AR; ui = AI; vr = BR; vi = BI;
        } else {
            // (a,b) <- (a*A - b*conj(B), a*B + b*conj(A))
            const float nar = fmaf(ur, AR, fmaf(-ui, AI, fmaf(-vr, BR, -vi * BI)));
            const float nai = fmaf(ur, AI, fmaf( ui, AR, fmaf( vr, BI, -vi * BR)));
            const float nbr = fmaf(ur, BR, fmaf(-ui, BI, fmaf( vr, AR,  vi * AI)));
            const float nbi = fmaf(ur, BI, fmaf( ui, BR, fmaf( vi, AR, -vr * AI)));
            ur = nar; ui = nai; vr = nbr; vi = nbi;
        }
    }

    g_grid[i] = make_float2(ur, ui);   // u00 at this node
}

// ---- Kernel 2: cubic Lagrange interpolation, 2 rows/thread/iter -------------
__global__ void __launch_bounds__(256, 8)
interp_kernel(const float2* __restrict__ th2, float* __restrict__ out, int n)
{
    __shared__ float2 G[GRID_PTS];   // 16416 B
    for (int i = threadIdx.x; i < GRID_PTS; i += 256)
        G[i] = g_grid[i];
    __syncthreads();

    // invh = GRID_N / pi, split for an accurate fractional position
    constexpr double INVH_D  = (double)GRID_N / 3.14159265358979323846;
    const float invh_hi = (float)INVH_D;
    const float invh_lo = (float)(INVH_D - (double)invh_hi);

    const int np = n >> 1;
    const int stride = gridDim.x * blockDim.x;
    float2* outr = reinterpret_cast<float2*>(out);
    float2* outi = reinterpret_cast<float2*>(out + n);

    for (int g = blockIdx.x * blockDim.x + threadIdx.x; g < np; g += stride) {
        const float2 tt = th2[g];
        float2 re, im;

#pragma unroll
        for (int r = 0; r < 2; ++r) {
            const float t = (r == 0) ? tt.x : tt.y;

            // u = t/h with ~1e-7 accuracy in the fraction
            const float p  = t * invh_hi;
            const float kf = floorf(p);
            const float e  = fmaf(t, invh_hi, -p) + t * invh_lo;
            const float f  = (p - kf) + e;
            const int   k  = (int)kf;          // nodes k-1..k+2 -> slots k..k+3

            // 4-point Lagrange weights at offset f in {-1,0,1,2}
            const float fm1 = f - 1.0f, fm2 = f - 2.0f, fp1 = f + 1.0f;
            const float t1  = f * fm1;          // f(f-1)
            const float t2  = fp1 * fm2;        // (f+1)(f-2)
            const float wm1 = (t1 * fm2) * (-1.0f / 6.0f);
            const float w2  = (t1 * fp1) * ( 1.0f / 6.0f);
            const float w0  = (t2 * fm1) * 0.5f;
            const float w1  = (t2 * f  ) * (-0.5f);

            const float2 g0 = G[k];
            const float2 g1 = G[k + 1];
            const float2 g2 = G[k + 2];
            const float2 g3 = G[k + 3];

            const float vr = fmaf(wm1, g0.x, fmaf(w0, g1.x, fmaf(w1, g2.x, w2 * g3.x)));
            const float vi = fmaf(wm1, g0.y, fmaf(w0, g1.y, fmaf(w1, g2.y, w2 * g3.y)));
            if (r == 0) { re.x = vr; im.x = vi; }
            else        { re.y = vr; im.y = vi; }
        }

        outr[g] = re;   // rows 2g, 2g+1
        outi[g] = im;
    }
}

// ---- launch -----------------------------------------------------------------
extern "C" void kernel_launch(void* const* d_in, const int* in_sizes, int n_in,
                              void* d_out, int out_size)
{
    const float* th   = (const float*)d_in[0];
    const float* phis = (const float*)d_in[1];
    float* out = (float*)d_out;
    const int n = in_sizes[0];  // B rows (even)

    fused_grid_kernel<<<(GRID_PTS + 255) / 256, 256>>>(phis);

    const int blocks = 148 * 8;   // 8 per SM
    interp_kernel<<<blocks, 256>>>(
        reinterpret_cast<const float2*>(th), out, n);
}